// round 5
// baseline (speedup 1.0000x reference)
#include <cuda_runtime.h>
#include <cstdint>

#define NN   100000
#define EE   1600000
#define IND  128
#define HIDD 256
#define OUTD 64

typedef unsigned long long ull;

// ---------------- scratch (device globals: allocation-free rule) -------------
__device__ int   g_src[EE];
__device__ int   g_dst[EE];
__device__ float g_cnt[NN];
__device__ float g_inv[NN];
__device__ float g_agg1[NN * IND];        // becomes mean in-place
__device__ float g_h[NN * HIDD];
__device__ float g_pq[NN * (2 * OUTD)];   // p | q
__device__ float g_agg2[NN * OUTD];
__device__ int   g_is64;

// ---------------- packed f32x2 helpers (sm_100+ plain-target feature) --------
__device__ __forceinline__ ull ffma2(ull a, ull b, ull c) {
    ull d;
    asm("fma.rn.f32x2 %0, %1, %2, %3;" : "=l"(d) : "l"(a), "l"(b), "l"(c));
    return d;
}
__device__ __forceinline__ ull pack2(float v) {
    ull d;
    asm("mov.b64 %0, {%1, %1};" : "=l"(d) : "f"(v));
    return d;
}
__device__ __forceinline__ void unpack2(ull p, float& lo, float& hi) {
    asm("mov.b64 {%0, %1}, %2;" : "=f"(lo), "=f"(hi) : "l"(p));
}

// ---------------- index dtype detection + conversion -------------------------
// jnp.int64 may arrive as int32 (jax x64 disabled) or int64. If int64, all
// high 32-bit words of the first values are 0 (indices < 100000).
__global__ void k_detect(const void* __restrict__ ei) {
    __shared__ int s_any;
    if (threadIdx.x == 0) s_any = 0;
    __syncthreads();
    const uint2* p = (const uint2*)ei;
    unsigned any = 0;
    for (int i = threadIdx.x; i < 2048; i += blockDim.x) any |= p[i].y;
    if (any) atomicOr(&s_any, 1);
    __syncthreads();
    if (threadIdx.x == 0) g_is64 = (s_any == 0) ? 1 : 0;
}

__global__ void k_convert(const void* __restrict__ ei) {
    int t = blockIdx.x * blockDim.x + threadIdx.x;
    if (t >= 2 * EE) return;
    int v;
    if (g_is64) v = (int)((const long long*)ei)[t];
    else        v = ((const int*)ei)[t];
    if (t < EE) g_src[t] = v;
    else        g_dst[t - EE] = v;
}

// ---------------- zero accumulators ------------------------------------------
__global__ void k_zero() {
    int t = blockIdx.x * blockDim.x + threadIdx.x;
    const int A1 = NN * (IND / 4);
    const int A2 = A1 + NN * (OUTD / 4);
    const int A3 = A2 + NN / 4;
    float4 z = make_float4(0.f, 0.f, 0.f, 0.f);
    if (t < A1)      ((float4*)g_agg1)[t] = z;
    else if (t < A2) ((float4*)g_agg2)[t - A1] = z;
    else if (t < A3) ((float4*)g_cnt)[t - A2] = z;
}

// ---------------- layer-1 scatter: agg1[dst] += x[src], cnt[dst] += 1 --------
__global__ void k_scatter1(const float* __restrict__ x) {
    int t = blockIdx.x * blockDim.x + threadIdx.x;
    if (t >= EE * 32) return;
    int e = t >> 5;
    int c = t & 31;
    int s = g_src[e];
    int d = g_dst[e];
    float4 v = ((const float4*)x)[s * 32 + c];
    atomicAdd(((float4*)g_agg1) + (d * 32 + c), v);
    if (c == 0) atomicAdd(&g_cnt[d], 1.0f);
}

// ---------------- mean --------------------------------------------------------
__global__ void k_mean() {
    int t = blockIdx.x * blockDim.x + threadIdx.x;
    if (t >= NN * 32) return;
    int i = t >> 5;
    int c = t & 31;
    float inv = 1.0f / fmaxf(g_cnt[i], 1.0f);
    float4* p = ((float4*)g_agg1) + t;
    float4 v = *p;
    v.x *= inv; v.y *= inv; v.z *= inv; v.w *= inv;
    *p = v;
    if (c == 0) g_inv[i] = inv;
}

// ======================= FFMA2 (f32x2) GEMM ==================================
// MODE 0: h = relu([mean|x] @ [W1l|W1r]^T + b1)   M=NN, N=256, K=256
// MODE 1: pq = h @ [W2l ; W2r]^T                  M=NN, N=128, K=256
// Block: 128 threads, output tile 128 rows x 128 cols, BK=16.
// Per thread: 8 rows x 16 cols, accumulated as 64 packed f32x2 row-pairs.
template <int MODE>
__global__ __launch_bounds__(128) void k_gemm_f2(
    const float* __restrict__ x,
    const float* __restrict__ Wa, const float* __restrict__ Wb,
    const float* __restrict__ bias)
{
    __shared__ float As[16][132];   // As[kk][row], row-pairs contiguous
    __shared__ float Bs[16][132];   // Bs[kk][col]

    const int tid = threadIdx.x;
    const int lk = tid & 3;        // which float4 along k (kk = lk*4..lk*4+3)
    const int lr = tid >> 2;       // 0..31
    const int tx = tid & 7;        // col group: cols tx*16..+15
    const int ty = tid >> 3;       // row group: rows ty*8..+7
    const int m0 = blockIdx.x * 128;
    const int j0 = blockIdx.y * 128;

    ull acc[4][16];                // acc[rp][c]: rows (ty*8+2rp, +1), col tx*16+c
#pragma unroll
    for (int rp = 0; rp < 4; rp++)
#pragma unroll
        for (int c = 0; c < 16; c++) acc[rp][c] = 0ull;

    for (int kt = 0; kt < 256; kt += 16) {
        // ---- stage A tile: 128 rows x 16 k, transposed into As[kk][row] ------
#pragma unroll
        for (int it = 0; it < 4; it++) {
            int row = lr + 32 * it;
            int gr = m0 + row;
            float4 v = make_float4(0.f, 0.f, 0.f, 0.f);
            if (gr < NN) {
                if (MODE == 0)
                    v = (kt < 128)
                        ? *(const float4*)(g_agg1 + gr * IND + kt + lk * 4)
                        : *(const float4*)(x + gr * IND + (kt - 128) + lk * 4);
                else
                    v = *(const float4*)(g_h + gr * HIDD + kt + lk * 4);
            }
            As[lk * 4 + 0][row] = v.x;
            As[lk * 4 + 1][row] = v.y;
            As[lk * 4 + 2][row] = v.z;
            As[lk * 4 + 3][row] = v.w;
        }
        // ---- stage B tile: 128 cols x 16 k -----------------------------------
#pragma unroll
        for (int it = 0; it < 4; it++) {
            int j = lr + 32 * it;                  // local output col 0..127
            const float* src;
            if (MODE == 0)
                src = (kt < 128) ? (Wa + (j0 + j) * IND + kt + lk * 4)
                                 : (Wb + (j0 + j) * IND + (kt - 128) + lk * 4);
            else
                src = (j < 64) ? (Wa + j * HIDD + kt + lk * 4)
                               : (Wb + (j - 64) * HIDD + kt + lk * 4);
            float4 v = *(const float4*)src;
            Bs[lk * 4 + 0][j] = v.x;
            Bs[lk * 4 + 1][j] = v.y;
            Bs[lk * 4 + 2][j] = v.z;
            Bs[lk * 4 + 3][j] = v.w;
        }
        __syncthreads();

        // ---- microkernel: 16 kk, 64 FFMA2 each -------------------------------
#pragma unroll
        for (int kk = 0; kk < 16; kk++) {
            ulonglong2 a01 = *(const ulonglong2*)&As[kk][ty * 8];
            ulonglong2 a23 = *(const ulonglong2*)&As[kk][ty * 8 + 4];
            ull ap[4] = {a01.x, a01.y, a23.x, a23.y};

            float4 b0 = *(const float4*)&Bs[kk][tx * 16];
            float4 b1 = *(const float4*)&Bs[kk][tx * 16 + 4];
            float4 b2 = *(const float4*)&Bs[kk][tx * 16 + 8];
            float4 b3 = *(const float4*)&Bs[kk][tx * 16 + 12];
            ull bd[16];
            bd[0]  = pack2(b0.x); bd[1]  = pack2(b0.y);
            bd[2]  = pack2(b0.z); bd[3]  = pack2(b0.w);
            bd[4]  = pack2(b1.x); bd[5]  = pack2(b1.y);
            bd[6]  = pack2(b1.z); bd[7]  = pack2(b1.w);
            bd[8]  = pack2(b2.x); bd[9]  = pack2(b2.y);
            bd[10] = pack2(b2.z); bd[11] = pack2(b2.w);
            bd[12] = pack2(b3.x); bd[13] = pack2(b3.y);
            bd[14] = pack2(b3.z); bd[15] = pack2(b3.w);

#pragma unroll
            for (int rp = 0; rp < 4; rp++)
#pragma unroll
                for (int c = 0; c < 16; c++)
                    acc[rp][c] = ffma2(ap[rp], bd[c], acc[rp][c]);
        }
        __syncthreads();
    }

    // ---- epilogue -------------------------------------------------------------
#pragma unroll
    for (int rp = 0; rp < 4; rp++) {
        float lo[16], hi[16];
#pragma unroll
        for (int c = 0; c < 16; c++) unpack2(acc[rp][c], lo[c], hi[c]);
#pragma unroll
        for (int h = 0; h < 2; h++) {
            int gr = m0 + ty * 8 + rp * 2 + h;
            if (gr >= NN) continue;
            const float* vv = h ? hi : lo;
            if (MODE == 0) {
                float* dst = g_h + gr * HIDD + j0 + tx * 16;
#pragma unroll
                for (int q = 0; q < 4; q++) {
                    float4 o;
                    o.x = fmaxf(vv[q * 4 + 0] + bias[j0 + tx * 16 + q * 4 + 0], 0.f);
                    o.y = fmaxf(vv[q * 4 + 1] + bias[j0 + tx * 16 + q * 4 + 1], 0.f);
                    o.z = fmaxf(vv[q * 4 + 2] + bias[j0 + tx * 16 + q * 4 + 2], 0.f);
                    o.w = fmaxf(vv[q * 4 + 3] + bias[j0 + tx * 16 + q * 4 + 3], 0.f);
                    *(float4*)(dst + q * 4) = o;
                }
            } else {
                float* dst = g_pq + gr * (2 * OUTD) + tx * 16;
#pragma unroll
                for (int q = 0; q < 4; q++)
                    *(float4*)(dst + q * 4) =
                        make_float4(vv[q * 4], vv[q * 4 + 1], vv[q * 4 + 2], vv[q * 4 + 3]);
            }
        }
    }
}

// ---------------- layer-2 scatter: agg2[dst] += p[src] -----------------------
__global__ void k_scatter2() {
    int t = blockIdx.x * blockDim.x + threadIdx.x;
    if (t >= EE * 16) return;
    int e = t >> 4;
    int c = t & 15;
    int s = g_src[e];
    int d = g_dst[e];
    float4 v = ((const float4*)g_pq)[s * 32 + c];
    atomicAdd(((float4*)g_agg2) + (d * 16 + c), v);
}

// ---------------- epilogue: out = agg2*inv + b2 + q --------------------------
__global__ void k_final(const float* __restrict__ b2, float* __restrict__ out) {
    int t = blockIdx.x * blockDim.x + threadIdx.x;
    if (t >= NN * 16) return;
    int i = t >> 4;
    int c = t & 15;
    float inv = g_inv[i];
    float4 a = ((const float4*)g_agg2)[t];
    float4 q = ((const float4*)g_pq)[i * 32 + 16 + c];
    float4 bb = ((const float4*)b2)[c];
    float4 r;
    r.x = fmaf(a.x, inv, bb.x) + q.x;
    r.y = fmaf(a.y, inv, bb.y) + q.y;
    r.z = fmaf(a.z, inv, bb.z) + q.z;
    r.w = fmaf(a.w, inv, bb.w) + q.w;
    ((float4*)out)[t] = r;
}

// ---------------- launch ------------------------------------------------------
extern "C" void kernel_launch(void* const* d_in, const int* in_sizes, int n_in,
                              void* d_out, int out_size) {
    const float* x   = (const float*)d_in[0];
    const void*  ei  = d_in[1];
    const float* W1l = (const float*)d_in[2];
    const float* b1  = (const float*)d_in[3];
    const float* W1r = (const float*)d_in[4];
    const float* W2l = (const float*)d_in[5];
    const float* b2  = (const float*)d_in[6];
    const float* W2r = (const float*)d_in[7];
    float* out = (float*)d_out;

    k_detect<<<1, 256>>>(ei);
    k_convert<<<(2 * EE + 255) / 256, 256>>>(ei);

    const int zero_elems = NN * (IND / 4) + NN * (OUTD / 4) + NN / 4;
    k_zero<<<(zero_elems + 255) / 256, 256>>>();

    k_scatter1<<<(EE * 32) / 256, 256>>>(x);
    k_mean<<<(NN * 32 + 255) / 256, 256>>>();

    const int MT = (NN + 127) / 128;   // 782
    k_gemm_f2<0><<<dim3(MT, 2), 128>>>(x, W1l, W1r, b1);
    k_gemm_f2<1><<<dim3(MT, 1), 128>>>(x, W2l, W2r, b1);

    k_scatter2<<<(EE * 16) / 256, 256>>>();
    k_final<<<(NN * 16 + 255) / 256, 256>>>(b2, out);
}

// round 6
// speedup vs baseline: 1.7818x; 1.7818x over previous
#include <cuda_runtime.h>
#include <cuda_bf16.h>
#include <cstdint>

#define NN   100000
#define EE   1600000
#define IND  128
#define HIDD 256
#define OUTD 64

// ---------------- scratch (device globals: allocation-free rule) -------------
__device__ int   g_src[EE];
__device__ int   g_dst[EE];
__device__ float g_cnt[NN];
__device__ float g_inv[NN];
__device__ float g_agg1[NN * IND];        // becomes mean in-place
__device__ float g_h[NN * HIDD];
__device__ float g_pq[NN * (2 * OUTD)];   // p | q
__device__ float g_agg2[NN * OUTD];
__device__ int   g_is64;

// ---------------- helpers -----------------------------------------------------
__device__ __forceinline__ uint32_t smem_u32(const void* p) {
    uint32_t a;
    asm("{ .reg .u64 t; cvta.to.shared.u64 t, %1; cvt.u32.u64 %0, t; }"
        : "=r"(a) : "l"(p));
    return a;
}
// pack two floats -> bf16x2 (lo in low half)
__device__ __forceinline__ uint32_t bf2(float lo, float hi) {
    uint32_t r;
    asm("cvt.rn.bf16x2.f32 %0, %1, %2;" : "=r"(r) : "f"(hi), "f"(lo));
    return r;
}
// round-to-nearest-bf16 value of v, as float
__device__ __forceinline__ float bfhi_f(float v) {
    uint32_t r;
    asm("cvt.rn.bf16x2.f32 %0, %1, %1;" : "=r"(r) : "f"(v));
    return __uint_as_float(r << 16);
}
__device__ __forceinline__ void ldsm4(uint32_t* r, uint32_t addr) {
    asm volatile("ldmatrix.sync.aligned.m8n8.x4.shared.b16 {%0,%1,%2,%3}, [%4];"
                 : "=r"(r[0]), "=r"(r[1]), "=r"(r[2]), "=r"(r[3]) : "r"(addr));
}
__device__ __forceinline__ void mma_bf16(float* d, const uint32_t* a,
                                         uint32_t b0, uint32_t b1) {
    asm volatile(
        "mma.sync.aligned.m16n8k16.row.col.f32.bf16.bf16.f32 "
        "{%0,%1,%2,%3}, {%4,%5,%6,%7}, {%8,%9}, {%0,%1,%2,%3};"
        : "+f"(d[0]), "+f"(d[1]), "+f"(d[2]), "+f"(d[3])
        : "r"(a[0]), "r"(a[1]), "r"(a[2]), "r"(a[3]), "r"(b0), "r"(b1));
}

// ---------------- index dtype detection + conversion -------------------------
__global__ void k_detect(const void* __restrict__ ei) {
    __shared__ int s_any;
    if (threadIdx.x == 0) s_any = 0;
    __syncthreads();
    const uint2* p = (const uint2*)ei;
    unsigned any = 0;
    for (int i = threadIdx.x; i < 2048; i += blockDim.x) any |= p[i].y;
    if (any) atomicOr(&s_any, 1);
    __syncthreads();
    if (threadIdx.x == 0) g_is64 = (s_any == 0) ? 1 : 0;
}

__global__ void k_convert(const void* __restrict__ ei) {
    int t = blockIdx.x * blockDim.x + threadIdx.x;
    if (t >= 2 * EE) return;
    int v;
    if (g_is64) v = (int)((const long long*)ei)[t];
    else        v = ((const int*)ei)[t];
    if (t < EE) g_src[t] = v;
    else        g_dst[t - EE] = v;
}

// ---------------- zero accumulators ------------------------------------------
__global__ void k_zero() {
    int t = blockIdx.x * blockDim.x + threadIdx.x;
    const int A1 = NN * (IND / 4);
    const int A2 = A1 + NN * (OUTD / 4);
    const int A3 = A2 + NN / 4;
    float4 z = make_float4(0.f, 0.f, 0.f, 0.f);
    if (t < A1)      ((float4*)g_agg1)[t] = z;
    else if (t < A2) ((float4*)g_agg2)[t - A1] = z;
    else if (t < A3) ((float4*)g_cnt)[t - A2] = z;
}

// ---------------- layer-1 scatter --------------------------------------------
__global__ void k_scatter1(const float* __restrict__ x) {
    int t = blockIdx.x * blockDim.x + threadIdx.x;
    if (t >= EE * 32) return;
    int e = t >> 5;
    int c = t & 31;
    int s = g_src[e];
    int d = g_dst[e];
    float4 v = ((const float4*)x)[s * 32 + c];
    atomicAdd(((float4*)g_agg1) + (d * 32 + c), v);
    if (c == 0) atomicAdd(&g_cnt[d], 1.0f);
}

// ---------------- mean --------------------------------------------------------
__global__ void k_mean() {
    int t = blockIdx.x * blockDim.x + threadIdx.x;
    if (t >= NN * 32) return;
    int i = t >> 5;
    int c = t & 31;
    float inv = 1.0f / fmaxf(g_cnt[i], 1.0f);
    float4* p = ((float4*)g_agg1) + t;
    float4 v = *p;
    v.x *= inv; v.y *= inv; v.z *= inv; v.w *= inv;
    *p = v;
    if (c == 0) g_inv[i] = inv;
}

// ======================= mma.sync bf16x2-split GEMM ==========================
// MODE 0: h = relu([mean|x] @ [W1l|W1r]^T + b1)   M=NN, N=256 (grid.y=2), K=256
// MODE 1: pq = h @ [W2l ; W2r]^T                  M=NN, N=128 (grid.y=1), K=256
// CTA: 256 thr, block tile 128x128, warp grid 4(M)x2(N), warp tile 32x64.
// fp32 = hi(bf16) + lo(bf16);  D += Ah*Bh + Ah*Bl + Al*Bh  (lo*lo dropped).
// smem: A/B tiles 128 x 64k bf16, XOR-swizzled (16B chunk ^= row&7).
template <int MODE>
__global__ __launch_bounds__(256) void k_gemm_mma(
    const float* __restrict__ x,
    const float* __restrict__ Wa, const float* __restrict__ Wb,
    const float* __restrict__ bias)
{
    extern __shared__ char smem[];
    const int OF_AH = 0, OF_AL = 16384, OF_BH = 32768, OF_BL = 49152;
    const uint32_t sb = smem_u32(smem);

    const int tid  = threadIdx.x;
    const int wid  = tid >> 5;
    const int lane = tid & 31;
    const int wm   = wid & 3;           // warp row block (32 rows)
    const int wn   = wid >> 2;          // warp col block (64 cols)
    const int m0   = blockIdx.x * 128;
    const int j0   = blockIdx.y * 128;  // 0 for MODE 1

    float acc[2][8][4];
#pragma unroll
    for (int a = 0; a < 2; a++)
#pragma unroll
        for (int b = 0; b < 8; b++)
#pragma unroll
            for (int c = 0; c < 4; c++) acc[a][b][c] = 0.f;

    // ldmatrix lane addressing precompute
    const int r8   = lane & 7;
    const int subm = lane >> 3;                 // 0..3

    for (int kt = 0; kt < 256; kt += 64) {
        // ---- stage A: 128 rows x 64 k, split hi/lo ---------------------------
#pragma unroll
        for (int i = 0; i < 8; i++) {
            int idx = tid + i * 256;            // 0..2047
            int row = idx >> 4;                 // 0..127
            int c4  = idx & 15;                 // float4 within row
            int gr  = m0 + row;
            float4 v = make_float4(0.f, 0.f, 0.f, 0.f);
            if (gr < NN) {
                if (MODE == 0)
                    v = (kt < 128)
                        ? *(const float4*)(g_agg1 + gr * IND + kt + c4 * 4)
                        : *(const float4*)(x + gr * IND + (kt - 128) + c4 * 4);
                else
                    v = *(const float4*)(g_h + gr * HIDD + kt + c4 * 4);
            }
            float h0 = bfhi_f(v.x), h1 = bfhi_f(v.y), h2 = bfhi_f(v.z), h3 = bfhi_f(v.w);
            uint2 uh, ul;
            uh.x = bf2(h0, h1);           uh.y = bf2(h2, h3);
            ul.x = bf2(v.x - h0, v.y - h1); ul.y = bf2(v.z - h2, v.w - h3);
            int chunk16 = c4 >> 1;              // 16B chunk along k
            int half    = c4 & 1;
            uint32_t byte = (uint32_t)(row * 128 + ((chunk16 ^ (row & 7)) * 16) + half * 8);
            *(uint2*)(smem + OF_AH + byte) = uh;
            *(uint2*)(smem + OF_AL + byte) = ul;
        }
        // ---- stage B: 128 cols x 64 k, split hi/lo ---------------------------
#pragma unroll
        for (int i = 0; i < 8; i++) {
            int idx = tid + i * 256;
            int row = idx >> 4;                 // output col 0..127 (local)
            int c4  = idx & 15;
            const float* src;
            if (MODE == 0)
                src = (kt < 128) ? (Wa + (j0 + row) * IND + kt + c4 * 4)
                                 : (Wb + (j0 + row) * IND + (kt - 128) + c4 * 4);
            else
                src = (row < 64) ? (Wa + row * HIDD + kt + c4 * 4)
                                 : (Wb + (row - 64) * HIDD + kt + c4 * 4);
            float4 v = *(const float4*)src;
            float h0 = bfhi_f(v.x), h1 = bfhi_f(v.y), h2 = bfhi_f(v.z), h3 = bfhi_f(v.w);
            uint2 uh, ul;
            uh.x = bf2(h0, h1);           uh.y = bf2(h2, h3);
            ul.x = bf2(v.x - h0, v.y - h1); ul.y = bf2(v.z - h2, v.w - h3);
            int chunk16 = c4 >> 1;
            int half    = c4 & 1;
            uint32_t byte = (uint32_t)(row * 128 + ((chunk16 ^ (row & 7)) * 16) + half * 8);
            *(uint2*)(smem + OF_BH + byte) = uh;
            *(uint2*)(smem + OF_BL + byte) = ul;
        }
        __syncthreads();

        // ---- 4 k16 steps ------------------------------------------------------
#pragma unroll
        for (int ks = 0; ks < 4; ks++) {
            const int cb = ks * 2;              // base 16B-chunk of this k16

            // A fragments: 2 m16 tiles, hi+lo
            uint32_t ah[2][4], al[2][4];
#pragma unroll
            for (int tm = 0; tm < 2; tm++) {
                int arow = wm * 32 + tm * 16 + (subm & 1) * 8 + r8;
                int achk = cb + (subm >> 1);
                uint32_t ab = (uint32_t)(arow * 128 + ((achk ^ (arow & 7)) * 16));
                ldsm4(ah[tm], sb + OF_AH + ab);
                ldsm4(al[tm], sb + OF_AL + ab);
            }
            // B fragments: 8 n8 tiles (4 x4-loads), hi+lo
            uint32_t bh[16], bl[16];
#pragma unroll
            for (int g = 0; g < 4; g++) {
                int brow = wn * 64 + g * 16 + (subm >> 1) * 8 + r8;
                int bchk = cb + (subm & 1);
                uint32_t bb = (uint32_t)(brow * 128 + ((bchk ^ (brow & 7)) * 16));
                ldsm4(&bh[g * 4], sb + OF_BH + bb);
                ldsm4(&bl[g * 4], sb + OF_BL + bb);
            }
#pragma unroll
            for (int tm = 0; tm < 2; tm++)
#pragma unroll
                for (int tn = 0; tn < 8; tn++) {
                    mma_bf16(acc[tm][tn], ah[tm], bh[tn * 2], bh[tn * 2 + 1]);
                    mma_bf16(acc[tm][tn], ah[tm], bl[tn * 2], bl[tn * 2 + 1]);
                    mma_bf16(acc[tm][tn], al[tm], bh[tn * 2], bh[tn * 2 + 1]);
                }
        }
        __syncthreads();
    }

    // ---- epilogue -------------------------------------------------------------
    const int qrow = lane >> 2;                 // 0..7
    const int qcol = (lane & 3) * 2;
#pragma unroll
    for (int tm = 0; tm < 2; tm++) {
#pragma unroll
        for (int half = 0; half < 2; half++) {
            int gr = m0 + wm * 32 + tm * 16 + half * 8 + qrow;
            if (gr >= NN) continue;
#pragma unroll
            for (int tn = 0; tn < 8; tn++) {
                int gc = j0 + wn * 64 + tn * 8 + qcol;
                float v0 = acc[tm][tn][half * 2 + 0];
                float v1 = acc[tm][tn][half * 2 + 1];
                if (MODE == 0) {
                    v0 = fmaxf(v0 + bias[gc], 0.f);
                    v1 = fmaxf(v1 + bias[gc + 1], 0.f);
                    *(float2*)(g_h + gr * HIDD + gc) = make_float2(v0, v1);
                } else {
                    *(float2*)(g_pq + gr * (2 * OUTD) + gc) = make_float2(v0, v1);
                }
            }
        }
    }
}

// ---------------- layer-2 scatter --------------------------------------------
__global__ void k_scatter2() {
    int t = blockIdx.x * blockDim.x + threadIdx.x;
    if (t >= EE * 16) return;
    int e = t >> 4;
    int c = t & 15;
    int s = g_src[e];
    int d = g_dst[e];
    float4 v = ((const float4*)g_pq)[s * 32 + c];
    atomicAdd(((float4*)g_agg2) + (d * 16 + c), v);
}

// ---------------- epilogue ----------------------------------------------------
__global__ void k_final(const float* __restrict__ b2, float* __restrict__ out) {
    int t = blockIdx.x * blockDim.x + threadIdx.x;
    if (t >= NN * 16) return;
    int i = t >> 4;
    int c = t & 15;
    float inv = g_inv[i];
    float4 a = ((const float4*)g_agg2)[t];
    float4 q = ((const float4*)g_pq)[i * 32 + 16 + c];
    float4 bb = ((const float4*)b2)[c];
    float4 r;
    r.x = fmaf(a.x, inv, bb.x) + q.x;
    r.y = fmaf(a.y, inv, bb.y) + q.y;
    r.z = fmaf(a.z, inv, bb.z) + q.z;
    r.w = fmaf(a.w, inv, bb.w) + q.w;
    ((float4*)out)[t] = r;
}

// ---------------- launch ------------------------------------------------------
extern "C" void kernel_launch(void* const* d_in, const int* in_sizes, int n_in,
                              void* d_out, int out_size) {
    const float* x   = (const float*)d_in[0];
    const void*  ei  = d_in[1];
    const float* W1l = (const float*)d_in[2];
    const float* b1  = (const float*)d_in[3];
    const float* W1r = (const float*)d_in[4];
    const float* W2l = (const float*)d_in[5];
    const float* b2  = (const float*)d_in[6];
    const float* W2r = (const float*)d_in[7];
    float* out = (float*)d_out;

    const int SMEM = 65536;
    static int configured = 0;
    cudaFuncSetAttribute(k_gemm_mma<0>,
                         cudaFuncAttributeMaxDynamicSharedMemorySize, SMEM);
    cudaFuncSetAttribute(k_gemm_mma<1>,
                         cudaFuncAttributeMaxDynamicSharedMemorySize, SMEM);
    (void)configured;

    k_detect<<<1, 256>>>(ei);
    k_convert<<<(2 * EE + 255) / 256, 256>>>(ei);

    const int zero_elems = NN * (IND / 4) + NN * (OUTD / 4) + NN / 4;
    k_zero<<<(zero_elems + 255) / 256, 256>>>();

    k_scatter1<<<(EE * 32) / 256, 256>>>(x);
    k_mean<<<(NN * 32 + 255) / 256, 256>>>();

    const int MT = (NN + 127) / 128;   // 782
    k_gemm_mma<0><<<dim3(MT, 2), 256, SMEM>>>(x, W1l, W1r, b1);
    k_gemm_mma<1><<<dim3(MT, 1), 256, SMEM>>>(x, W2l, W2r, b1);

    k_scatter2<<<(EE * 16) / 256, 256>>>();
    k_final<<<(NN * 16 + 255) / 256, 256>>>(b2, out);
}

// round 7
// speedup vs baseline: 2.3968x; 1.3452x over previous
#include <cuda_runtime.h>
#include <cuda_bf16.h>
#include <cstdint>

#define NN   100000
#define EE   1600000
#define IND  128
#define HIDD 256
#define OUTD 64
#define NB_SCAN 196   // ceil(NN/512)

// ---------------- scratch (device globals: allocation-free rule) -------------
__device__ int   g_src[EE];
__device__ int   g_dst[EE];
__device__ int   g_eidx[EE];              // CSR: src ids grouped by dst
__device__ int   g_count[NN];
__device__ int   g_cursor[NN];
__device__ int   g_bsum[NB_SCAN];
__device__ int   g_off[NN + 1];
__device__ float g_inv[NN];
__device__ float g_agg1[NN * IND];        // layer-1 mean
__device__ float g_h[NN * HIDD];
__device__ float g_pq[NN * (2 * OUTD)];   // p | q
__device__ int   g_is64;

// ---------------- helpers -----------------------------------------------------
__device__ __forceinline__ uint32_t smem_u32(const void* p) {
    uint32_t a;
    asm("{ .reg .u64 t; cvta.to.shared.u64 t, %1; cvt.u32.u64 %0, t; }"
        : "=r"(a) : "l"(p));
    return a;
}
__device__ __forceinline__ uint32_t bf2(float lo, float hi) {
    uint32_t r;
    asm("cvt.rn.bf16x2.f32 %0, %1, %2;" : "=r"(r) : "f"(hi), "f"(lo));
    return r;
}
__device__ __forceinline__ float bfhi_f(float v) {
    uint32_t r;
    asm("cvt.rn.bf16x2.f32 %0, %1, %1;" : "=r"(r) : "f"(v));
    return __uint_as_float(r << 16);
}
__device__ __forceinline__ void ldsm4(uint32_t* r, uint32_t addr) {
    asm volatile("ldmatrix.sync.aligned.m8n8.x4.shared.b16 {%0,%1,%2,%3}, [%4];"
                 : "=r"(r[0]), "=r"(r[1]), "=r"(r[2]), "=r"(r[3]) : "r"(addr));
}
__device__ __forceinline__ void mma_bf16(float* d, const uint32_t* a,
                                         uint32_t b0, uint32_t b1) {
    asm volatile(
        "mma.sync.aligned.m16n8k16.row.col.f32.bf16.bf16.f32 "
        "{%0,%1,%2,%3}, {%4,%5,%6,%7}, {%8,%9}, {%0,%1,%2,%3};"
        : "+f"(d[0]), "+f"(d[1]), "+f"(d[2]), "+f"(d[3])
        : "r"(a[0]), "r"(a[1]), "r"(a[2]), "r"(a[3]), "r"(b0), "r"(b1));
}

// ---------------- index dtype detection ---------------------------------------
__global__ void k_detect(const void* __restrict__ ei) {
    __shared__ int s_any;
    if (threadIdx.x == 0) s_any = 0;
    __syncthreads();
    const uint2* p = (const uint2*)ei;
    unsigned any = 0;
    for (int i = threadIdx.x; i < 2048; i += blockDim.x) any |= p[i].y;
    if (any) atomicOr(&s_any, 1);
    __syncthreads();
    if (threadIdx.x == 0) g_is64 = (s_any == 0) ? 1 : 0;
}

// zero count + cursor
__global__ void k_zero_cnt() {
    int t = blockIdx.x * blockDim.x + threadIdx.x;
    if (t < NN) { g_count[t] = 0; g_cursor[t] = 0; }
}

// convert indices + histogram of dst
__global__ void k_convert(const void* __restrict__ ei) {
    int t = blockIdx.x * blockDim.x + threadIdx.x;
    if (t >= 2 * EE) return;
    int v;
    if (g_is64) v = (int)((const long long*)ei)[t];
    else        v = ((const int*)ei)[t];
    if (t < EE) g_src[t] = v;
    else { g_dst[t - EE] = v; atomicAdd(&g_count[v], 1); }
}

// ---------------- exclusive scan of g_count -> g_off --------------------------
__global__ void k_s1() {
    int t = blockIdx.x * 512 + threadIdx.x;
    int v = (t < NN) ? g_count[t] : 0;
    __shared__ int sw[16];
    int wid = threadIdx.x >> 5, lid = threadIdx.x & 31;
    int s = v;
#pragma unroll
    for (int o = 16; o > 0; o >>= 1) s += __shfl_down_sync(0xffffffff, s, o);
    if (lid == 0) sw[wid] = s;
    __syncthreads();
    if (wid == 0) {
        int x = (lid < 16) ? sw[lid] : 0;
#pragma unroll
        for (int o = 16; o > 0; o >>= 1) x += __shfl_down_sync(0xffffffff, x, o);
        if (lid == 0) g_bsum[blockIdx.x] = x;
    }
}
__global__ void k_s2() {
    if (threadIdx.x == 0) {
        int run = 0;
        for (int i = 0; i < NB_SCAN; i++) { int v = g_bsum[i]; g_bsum[i] = run; run += v; }
        g_off[NN] = run;
    }
}
__global__ void k_s3() {
    __shared__ int sm[512];
    int t = blockIdx.x * 512 + threadIdx.x;
    int v = (t < NN) ? g_count[t] : 0;
    sm[threadIdx.x] = v;
    __syncthreads();
#pragma unroll
    for (int o = 1; o < 512; o <<= 1) {
        int tmp = (threadIdx.x >= o) ? sm[threadIdx.x - o] : 0;
        __syncthreads();
        sm[threadIdx.x] += tmp;
        __syncthreads();
    }
    if (t < NN) g_off[t] = sm[threadIdx.x] - v + g_bsum[blockIdx.x];
}

// ---------------- bucket-scatter edge ids -------------------------------------
__global__ void k_build() {
    int t = blockIdx.x * blockDim.x + threadIdx.x;
    if (t >= EE) return;
    int d = g_dst[t];
    int p = g_off[d] + atomicAdd(&g_cursor[d], 1);
    g_eidx[p] = g_src[t];
}

// ---------------- layer-1 segmented mean: warp per node -----------------------
__global__ void k_reduce1(const float* __restrict__ x) {
    int wgl = (blockIdx.x * blockDim.x + threadIdx.x) >> 5;
    int lane = threadIdx.x & 31;
    if (wgl >= NN) return;
    int beg = g_off[wgl], end = g_off[wgl + 1];
    float4 acc = make_float4(0.f, 0.f, 0.f, 0.f);
    for (int base = beg; base < end; base += 32) {
        int rem = end - base;
        int eid = (lane < rem) ? g_eidx[base + lane] : 0;
        int cnt = rem < 32 ? rem : 32;
#pragma unroll 4
        for (int j = 0; j < cnt; j++) {
            int s = __shfl_sync(0xffffffff, eid, j);
            float4 v = ((const float4*)x)[s * 32 + lane];
            acc.x += v.x; acc.y += v.y; acc.z += v.z; acc.w += v.w;
        }
    }
    float inv = 1.0f / fmaxf((float)(end - beg), 1.0f);
    acc.x *= inv; acc.y *= inv; acc.z *= inv; acc.w *= inv;
    ((float4*)g_agg1)[wgl * 32 + lane] = acc;
    if (lane == 0) g_inv[wgl] = inv;
}

// ======================= mma.sync bf16x2-split GEMM ==========================
// MODE 0: h = relu([mean|x] @ [W1l|W1r]^T + b1)   M=NN, N=256 (grid.y=2), K=256
// MODE 1: pq = h @ [W2l ; W2r]^T                  M=NN, N=128 (grid.y=1), K=256
template <int MODE>
__global__ __launch_bounds__(256) void k_gemm_mma(
    const float* __restrict__ x,
    const float* __restrict__ Wa, const float* __restrict__ Wb,
    const float* __restrict__ bias)
{
    extern __shared__ char smem[];
    const int OF_AH = 0, OF_AL = 16384, OF_BH = 32768, OF_BL = 49152;
    const uint32_t sb = smem_u32(smem);

    const int tid  = threadIdx.x;
    const int wid  = tid >> 5;
    const int lane = tid & 31;
    const int wm   = wid & 3;
    const int wn   = wid >> 2;
    const int m0   = blockIdx.x * 128;
    const int j0   = blockIdx.y * 128;

    float acc[2][8][4];
#pragma unroll
    for (int a = 0; a < 2; a++)
#pragma unroll
        for (int b = 0; b < 8; b++)
#pragma unroll
            for (int c = 0; c < 4; c++) acc[a][b][c] = 0.f;

    const int r8   = lane & 7;
    const int subm = lane >> 3;

    for (int kt = 0; kt < 256; kt += 64) {
#pragma unroll
        for (int i = 0; i < 8; i++) {
            int idx = tid + i * 256;
            int row = idx >> 4;
            int c4  = idx & 15;
            int gr  = m0 + row;
            float4 v = make_float4(0.f, 0.f, 0.f, 0.f);
            if (gr < NN) {
                if (MODE == 0)
                    v = (kt < 128)
                        ? *(const float4*)(g_agg1 + gr * IND + kt + c4 * 4)
                        : *(const float4*)(x + gr * IND + (kt - 128) + c4 * 4);
                else
                    v = *(const float4*)(g_h + gr * HIDD + kt + c4 * 4);
            }
            float h0 = bfhi_f(v.x), h1 = bfhi_f(v.y), h2 = bfhi_f(v.z), h3 = bfhi_f(v.w);
            uint2 uh, ul;
            uh.x = bf2(h0, h1);             uh.y = bf2(h2, h3);
            ul.x = bf2(v.x - h0, v.y - h1); ul.y = bf2(v.z - h2, v.w - h3);
            int chunk16 = c4 >> 1;
            int half    = c4 & 1;
            uint32_t byte = (uint32_t)(row * 128 + ((chunk16 ^ (row & 7)) * 16) + half * 8);
            *(uint2*)(smem + OF_AH + byte) = uh;
            *(uint2*)(smem + OF_AL + byte) = ul;
        }
#pragma unroll
        for (int i = 0; i < 8; i++) {
            int idx = tid + i * 256;
            int row = idx >> 4;
            int c4  = idx & 15;
            const float* src;
            if (MODE == 0)
                src = (kt < 128) ? (Wa + (j0 + row) * IND + kt + c4 * 4)
                                 : (Wb + (j0 + row) * IND + (kt - 128) + c4 * 4);
            else
                src = (row < 64) ? (Wa + row * HIDD + kt + c4 * 4)
                                 : (Wb + (row - 64) * HIDD + kt + c4 * 4);
            float4 v = *(const float4*)src;
            float h0 = bfhi_f(v.x), h1 = bfhi_f(v.y), h2 = bfhi_f(v.z), h3 = bfhi_f(v.w);
            uint2 uh, ul;
            uh.x = bf2(h0, h1);             uh.y = bf2(h2, h3);
            ul.x = bf2(v.x - h0, v.y - h1); ul.y = bf2(v.z - h2, v.w - h3);
            int chunk16 = c4 >> 1;
            int half    = c4 & 1;
            uint32_t byte = (uint32_t)(row * 128 + ((chunk16 ^ (row & 7)) * 16) + half * 8);
            *(uint2*)(smem + OF_BH + byte) = uh;
            *(uint2*)(smem + OF_BL + byte) = ul;
        }
        __syncthreads();

#pragma unroll
        for (int ks = 0; ks < 4; ks++) {
            const int cb = ks * 2;
            uint32_t ah[2][4], al[2][4];
#pragma unroll
            for (int tm = 0; tm < 2; tm++) {
                int arow = wm * 32 + tm * 16 + (subm & 1) * 8 + r8;
                int achk = cb + (subm >> 1);
                uint32_t ab = (uint32_t)(arow * 128 + ((achk ^ (arow & 7)) * 16));
                ldsm4(ah[tm], sb + OF_AH + ab);
                ldsm4(al[tm], sb + OF_AL + ab);
            }
            uint32_t bh[16], bl[16];
#pragma unroll
            for (int g = 0; g < 4; g++) {
                int brow = wn * 64 + g * 16 + (subm >> 1) * 8 + r8;
                int bchk = cb + (subm & 1);
                uint32_t bb = (uint32_t)(brow * 128 + ((bchk ^ (brow & 7)) * 16));
                ldsm4(&bh[g * 4], sb + OF_BH + bb);
                ldsm4(&bl[g * 4], sb + OF_BL + bb);
            }
#pragma unroll
            for (int tm = 0; tm < 2; tm++)
#pragma unroll
                for (int tn = 0; tn < 8; tn++) {
                    mma_bf16(acc[tm][tn], ah[tm], bh[tn * 2], bh[tn * 2 + 1]);
                    mma_bf16(acc[tm][tn], ah[tm], bl[tn * 2], bl[tn * 2 + 1]);
                    mma_bf16(acc[tm][tn], al[tm], bh[tn * 2], bh[tn * 2 + 1]);
                }
        }
        __syncthreads();
    }

    const int qrow = lane >> 2;
    const int qcol = (lane & 3) * 2;
#pragma unroll
    for (int tm = 0; tm < 2; tm++) {
#pragma unroll
        for (int half = 0; half < 2; half++) {
            int gr = m0 + wm * 32 + tm * 16 + half * 8 + qrow;
            if (gr >= NN) continue;
#pragma unroll
            for (int tn = 0; tn < 8; tn++) {
                int gc = j0 + wn * 64 + tn * 8 + qcol;
                float v0 = acc[tm][tn][half * 2 + 0];
                float v1 = acc[tm][tn][half * 2 + 1];
                if (MODE == 0) {
                    v0 = fmaxf(v0 + bias[gc], 0.f);
                    v1 = fmaxf(v1 + bias[gc + 1], 0.f);
                    *(float2*)(g_h + gr * HIDD + gc) = make_float2(v0, v1);
                } else {
                    *(float2*)(g_pq + gr * (2 * OUTD) + gc) = make_float2(v0, v1);
                }
            }
        }
    }
}

// ---------------- layer-2 segmented mean + epilogue: warp per node ------------
__global__ void k_reduce2(const float* __restrict__ b2, float* __restrict__ out) {
    int wgl = (blockIdx.x * blockDim.x + threadIdx.x) >> 5;
    int lane = threadIdx.x & 31;
    if (wgl >= NN) return;
    int beg = g_off[wgl], end = g_off[wgl + 1];
    float2 acc = make_float2(0.f, 0.f);
    for (int base = beg; base < end; base += 32) {
        int rem = end - base;
        int eid = (lane < rem) ? g_eidx[base + lane] : 0;
        int cnt = rem < 32 ? rem : 32;
#pragma unroll 4
        for (int j = 0; j < cnt; j++) {
            int s = __shfl_sync(0xffffffff, eid, j);
            float2 v = ((const float2*)g_pq)[s * 64 + lane];   // p half
            acc.x += v.x; acc.y += v.y;
        }
    }
    float inv = g_inv[wgl];
    float2 q  = ((const float2*)g_pq)[wgl * 64 + 32 + lane];   // q half
    float2 bb = ((const float2*)b2)[lane];
    float2 r;
    r.x = fmaf(acc.x, inv, bb.x) + q.x;
    r.y = fmaf(acc.y, inv, bb.y) + q.y;
    ((float2*)out)[wgl * 32 + lane] = r;
}

// ---------------- launch ------------------------------------------------------
extern "C" void kernel_launch(void* const* d_in, const int* in_sizes, int n_in,
                              void* d_out, int out_size) {
    const float* x   = (const float*)d_in[0];
    const void*  ei  = d_in[1];
    const float* W1l = (const float*)d_in[2];
    const float* b1  = (const float*)d_in[3];
    const float* W1r = (const float*)d_in[4];
    const float* W2l = (const float*)d_in[5];
    const float* b2  = (const float*)d_in[6];
    const float* W2r = (const float*)d_in[7];
    float* out = (float*)d_out;

    const int SMEM = 65536;
    cudaFuncSetAttribute(k_gemm_mma<0>,
                         cudaFuncAttributeMaxDynamicSharedMemorySize, SMEM);
    cudaFuncSetAttribute(k_gemm_mma<1>,
                         cudaFuncAttributeMaxDynamicSharedMemorySize, SMEM);

    k_detect<<<1, 256>>>(ei);
    k_zero_cnt<<<(NN + 255) / 256, 256>>>();
    k_convert<<<(2 * EE + 255) / 256, 256>>>(ei);

    k_s1<<<NB_SCAN, 512>>>();
    k_s2<<<1, 32>>>();
    k_s3<<<NB_SCAN, 512>>>();
    k_build<<<(EE + 255) / 256, 256>>>();

    k_reduce1<<<(NN * 32 + 255) / 256, 256>>>(x);

    const int MT = (NN + 127) / 128;   // 782
    k_gemm_mma<0><<<dim3(MT, 2), 256, SMEM>>>(x, W1l, W1r, b1);
    k_gemm_mma<1><<<dim3(MT, 1), 256, SMEM>>>(x, W2l, W2r, b1);

    k_reduce2<<<(NN * 32 + 255) / 256, 256>>>(b2, out);
}